// round 17
// baseline (speedup 1.0000x reference)
#include <cuda_runtime.h>
#include <cuda_fp16.h>
#include <cstdint>

#define NN 524288   // nodes
#define DD 256      // input dim
#define HH 128      // hidden dim
#define BB 2048     // segments

// ---------------- scratch (device globals; no allocation allowed) ----------
__device__ float    g_segsum[BB];           // per-segment sum of exp (atomics)
__device__ uint32_t g_w1ph[(DD / 2) * HH];  // permuted half2 W1

// ---------------- helpers ---------------------------------------------------
__device__ __forceinline__ float tanha(float x) {
    float y;
    asm("tanh.approx.f32 %0, %1;" : "=f"(y) : "f"(x));
    return y;
}
__device__ __forceinline__ uint32_t smem_u32(const void* p) {
    uint32_t a;
    asm("{ .reg .u64 t; cvta.to.shared.u64 t, %1; cvt.u32.u64 %0, t; }" : "=r"(a) : "l"(p));
    return a;
}
__device__ __forceinline__ uint32_t pack_h2(float lo, float hi) {
    __half2 h = __floats2half2_rn(lo, hi);
    return *(uint32_t*)&h;
}
#define CP16(dst, src)  asm volatile("cp.async.ca.shared.global [%0], [%1], 16;" :: "r"(dst), "l"(src) : "memory")
#define CP_COMMIT()     asm volatile("cp.async.commit_group;" ::: "memory")
#define CP_WAIT(n)      asm volatile("cp.async.wait_group %0;" :: "n"(n) : "memory")

__device__ __forceinline__ void mma_f16(float& c0, float& c1, float& c2, float& c3,
                                        uint32_t a0, uint32_t a1, uint32_t a2, uint32_t a3,
                                        uint32_t b0, uint32_t b1) {
    asm("mma.sync.aligned.m16n8k16.row.col.f32.f16.f16.f32 "
        "{%0,%1,%2,%3}, {%4,%5,%6,%7}, {%8,%9}, {%0,%1,%2,%3};"
        : "+f"(c0), "+f"(c1), "+f"(c2), "+f"(c3)
        : "r"(a0), "r"(a1), "r"(a2), "r"(a3), "r"(b0), "r"(b1));
}

__device__ __forceinline__ void ldsm_x4(uint32_t& r0, uint32_t& r1, uint32_t& r2, uint32_t& r3,
                                        uint32_t addr) {
    asm volatile("ldmatrix.sync.aligned.m8n8.x4.shared.b16 {%0,%1,%2,%3}, [%4];"
                 : "=r"(r0), "=r"(r1), "=r"(r2), "=r"(r3) : "r"(addr));
}

// ---------------- kernel Z: zero out + segsum -------------------------------
__global__ void zero_kernel(float* __restrict__ out) {
    out[(size_t)blockIdx.x * DD + threadIdx.x] = 0.0f;
    if (threadIdx.x == 0) g_segsum[blockIdx.x] = 0.0f;
}

// ---------------- kernel 0: W1 -> permuted packed half2 (one-shot) ---------
__global__ void w1h_kernel(const float* __restrict__ W1) {
    int k2 = blockIdx.x;         // 0..127
    int c  = threadIdx.x;        // 0..127
    g_w1ph[k2 * HH + (c & 7) * 16 + (c >> 3)] =
        pack_h2(W1[(2 * k2) * HH + c], W1[(2 * k2 + 1) * HH + c]);
}

// ---------------- kernel A: FUSED scores + pooling ---------------------------
// 512 threads (16 warps), 1 CTA/SM. CTA tile: 256 nodes x 128 cols.
// Warp tile: 32 nodes x 64 cols (wid&7 = node slice, wid>>3 = column half).
// x tile PERSISTENT in smem as fp16 (node stride 132 half2-words): used first
// as MMA A-operand (ldmatrix), then re-read in the in-kernel pooling phase.
// Softmax: e = __expf(score) (bounded scores, unshifted-exp validated);
// partial weighted sums + Z flushed via coalesced atomics; normalize kernel
// divides by Z afterwards.
#define K2C 16
#define XS_STRIDE  132                     // half2 words per node row (128+4 pad)
#define X_BYTES    (256 * XS_STRIDE * 4)   // 135168
#define W1P_STRIDE 132
#define W1BUF_B (K2C * W1P_STRIDE * 4)     // 8448 B
#define OFF_X    0
#define OFF_W1   X_BYTES                   // 135168
#define OFF_B1   (OFF_W1 + 2 * W1BUF_B)    // 152064
#define OFF_W2   (OFF_B1 + 512)
#define OFF_PART (OFF_W2 + 512)            // 256 floats
#define OFF_EW   (OFF_PART + 1024)         // 256 floats
#define OFF_BAT  (OFF_EW + 1024)           // 256 ints
#define OFF_B2   (OFF_BAT + 1024)
#define SMEM_A_BYTES (OFF_B2 + 16)         // ~152.6 KB -> 1 CTA/SM

__global__ void __launch_bounds__(512, 1)
fused_kernel(const float* __restrict__ x,
             const int* __restrict__ batch,
             const float* __restrict__ b1,
             const float* __restrict__ W2,
             const float* __restrict__ b2,
             float* __restrict__ out) {
    extern __shared__ char smem[];
    const uint32_t sb = smem_u32(smem);

    float* b1s  = (float*)(smem + OFF_B1);
    float* w2s  = (float*)(smem + OFF_W2);
    float* part = (float*)(smem + OFF_PART);
    float* ew   = (float*)(smem + OFF_EW);
    int*   sbat = (int*)(smem + OFF_BAT);

    const int tid  = threadIdx.x;
    const int lane = tid & 31;
    const int wid  = tid >> 5;
    const int t    = lane & 3;          // k2 row within group
    const int g    = lane >> 2;         // group id
    const int wn   = (wid & 7) * 32;    // warp node base
    const int chf  = wid >> 3;          // column half
    const int n0   = blockIdx.x * 256;

    if (tid < 128) { b1s[tid] = b1[tid]; w2s[tid] = W2[tid]; }
    if (tid < 256) { sbat[tid] = batch[n0 + tid]; }
    if (tid == 0)  { ((float*)(smem + OFF_B2))[0] = b2[0]; }

    float acc[2][8][4];
    #pragma unroll
    for (int ra = 0; ra < 2; ++ra)
        #pragma unroll
        for (int j = 0; j < 8; ++j)
            #pragma unroll
            for (int r = 0; r < 4; ++r) acc[ra][j][r] = 0.0f;

    const float4* x4   = (const float4*)x;
    const char*   wsrc = (const char*)g_w1ph;

    // staging decompositions
    const int xnode = tid >> 1, xjj = tid & 1;   // x: node, j' = xjj + 2i
    const int wrow  = tid >> 5, wq  = tid & 31;  // W1: k2-row 0..15, 16B group

    // ldmatrix per-lane address pieces
    const uint32_t lm_row = (uint32_t)(wn + (lane & 15)) * (XS_STRIDE * 4)
                          + (uint32_t)(lane >> 4) * 16;

    // ---- prologue: cp.async W1 chunk 0 -> wbuf0; LDG x chunk 0 ----
    CP16(sb + OFF_W1 + (uint32_t)(wrow * W1P_STRIDE + 4 * wq) * 4,
         wsrc + (size_t)(wrow * HH + 4 * wq) * 4);
    CP_COMMIT();

    float4 rx[4];
    #pragma unroll
    for (int i = 0; i < 2; ++i) {
        int jp = xjj + 2 * i;
        rx[2 * i]     = x4[(size_t)(n0 + xnode) * 64 + 2 * jp];
        rx[2 * i + 1] = x4[(size_t)(n0 + xnode) * 64 + 2 * jp + 1];
    }

    for (int ch = 0; ch < 8; ++ch) {
        const int wbuf = ch & 1;
        uint32_t* xb  = (uint32_t*)(smem + OFF_X);
        uint32_t* w1b = (uint32_t*)(smem + OFF_W1 + wbuf * W1BUF_B);

        // ---- store staged x chunk into persistent tile (cvt half2, STS.128)
        #pragma unroll
        for (int i = 0; i < 2; ++i) {
            int jp = xjj + 2 * i;
            float4 f0 = rx[2 * i], f1 = rx[2 * i + 1];
            uint4 u;
            u.x = pack_h2(f0.x, f0.y); u.y = pack_h2(f0.z, f0.w);
            u.z = pack_h2(f1.x, f1.y); u.w = pack_h2(f1.z, f1.w);
            *(uint4*)(xb + xnode * XS_STRIDE + ch * 16 + 4 * jp) = u;
        }

        // ---- issue next chunk's loads ----
        if (ch < 7) {
            const uint32_t wo = OFF_W1 + (wbuf ^ 1) * W1BUF_B;
            CP16(sb + wo + (uint32_t)(wrow * W1P_STRIDE + 4 * wq) * 4,
                 wsrc + (size_t)(((ch + 1) * K2C + wrow) * HH + 4 * wq) * 4);
            CP_COMMIT();
            #pragma unroll
            for (int i = 0; i < 2; ++i) {
                int jp = xjj + 2 * i;
                rx[2 * i]     = x4[(size_t)(n0 + xnode) * 64 + (ch + 1) * 8 + 2 * jp];
                rx[2 * i + 1] = x4[(size_t)(n0 + xnode) * 64 + (ch + 1) * 8 + 2 * jp + 1];
            }
            CP_WAIT(1);   // chunk ch's W1 complete; ch+1 in flight
        } else {
            CP_WAIT(0);
        }
        __syncthreads();

        // ---- compute 2 k-steps (K=16 each) ----
        #pragma unroll
        for (int ks = 0; ks < 2; ++ks) {
            const int k2l = ks * 8;
            uint32_t ax[2][4];
            #pragma unroll
            for (int ra = 0; ra < 2; ++ra) {
                uint32_t addr = sb + OFF_X + lm_row
                              + (uint32_t)(16 * ra) * (XS_STRIDE * 4)
                              + (uint32_t)((ch * 16 + k2l) * 4);
                ldsm_x4(ax[ra][0], ax[ra][1], ax[ra][2], ax[ra][3], addr);
            }
            const uint32_t* r0 = w1b + (k2l + t) * W1P_STRIDE + g * 16 + chf * 8;
            const uint32_t* r1 = r0 + 4 * W1P_STRIDE;
            uint4 u0 = *(const uint4*)(r0);
            uint4 u1 = *(const uint4*)(r0 + 4);
            uint4 v0 = *(const uint4*)(r1);
            uint4 v1 = *(const uint4*)(r1 + 4);
            uint32_t bu[8] = {u0.x, u0.y, u0.z, u0.w, u1.x, u1.y, u1.z, u1.w};
            uint32_t bv[8] = {v0.x, v0.y, v0.z, v0.w, v1.x, v1.y, v1.z, v1.w};

            #pragma unroll
            for (int ra = 0; ra < 2; ++ra) {
                #pragma unroll
                for (int j = 0; j < 8; ++j) {
                    mma_f16(acc[ra][j][0], acc[ra][j][1], acc[ra][j][2], acc[ra][j][3],
                            ax[ra][0], ax[ra][1], ax[ra][2], ax[ra][3],
                            bu[j], bv[j]);
                }
            }
        }
        __syncthreads();   // W1 WAR across double buffer
    }

    // ---- epilogue: +b1, tanh, dot W2, reduce over t, combine col halves ----
    float p[4] = {0.f, 0.f, 0.f, 0.f};
    #pragma unroll
    for (int ra = 0; ra < 2; ++ra) {
        #pragma unroll
        for (int j = 0; j < 8; ++j) {
            #pragma unroll
            for (int rr = 0; rr < 2; ++rr) {
                int cc = (chf * 8 + j) * 8 + 2 * t + rr;
                float bb = b1s[cc], ww = w2s[cc];
                p[2 * ra]     += tanha(acc[ra][j][rr]     + bb) * ww;
                p[2 * ra + 1] += tanha(acc[ra][j][2 + rr] + bb) * ww;
            }
        }
    }
    #pragma unroll
    for (int i = 0; i < 4; ++i) {
        p[i] += __shfl_xor_sync(0xffffffffu, p[i], 1);
        p[i] += __shfl_xor_sync(0xffffffffu, p[i], 2);
    }
    if (t == 0 && chf == 0) {
        #pragma unroll
        for (int i = 0; i < 4; ++i) part[wn + g + 8 * i] = p[i];
    }
    __syncthreads();
    if (t == 0 && chf == 1) {
        float bb2 = ((float*)(smem + OFF_B2))[0];
        #pragma unroll
        for (int i = 0; i < 4; ++i) {
            int node = wn + g + 8 * i;
            float score = part[node] + p[i] + bb2;
            ew[node] = __expf(score);   // bounded: |score| <= ~11.4
        }
    }
    __syncthreads();

    // ---- in-kernel pooling: stream persistent fp16 x tile from smem --------
    // thread -> dim d = tid&255; group (tid>>8) handles 128 nodes.
    // Per-segment runs (sorted batch => warp-uniform flushes) accumulated and
    // flushed with coalesced atomicAdd into zeroed out; Z into g_segsum.
    {
        const int d   = tid & 255;
        const int grp = tid >> 8;
        const int j0  = grp * 128;
        const __half* xh = (const __half*)(smem + OFF_X);

        int   cur = sbat[j0];
        float pacc = 0.0f, z = 0.0f;
        #pragma unroll 4
        for (int j = 0; j < 128; ++j) {
            int n = j0 + j;
            int s = sbat[n];
            if (s != cur) {
                atomicAdd(&out[(size_t)cur * DD + d], pacc);
                if (d == 0) atomicAdd(&g_segsum[cur], z);
                pacc = 0.0f; z = 0.0f; cur = s;
            }
            float e  = ew[n];
            float xv = __half2float(xh[n * (2 * XS_STRIDE) + d]);
            pacc += e * xv;
            z += e;
        }
        atomicAdd(&out[(size_t)cur * DD + d], pacc);
        if (d == 0) atomicAdd(&g_segsum[cur], z);
    }
}

// ---------------- kernel N: normalize out by per-segment Z ------------------
__global__ void normalize_kernel(float* __restrict__ out) {
    const int b = blockIdx.x;
    const int d = threadIdx.x;
    float Z = g_segsum[b];
    float f = (Z > 0.0f) ? (1.0f / Z) : 0.0f;
    out[(size_t)b * DD + d] *= f;
}

// ---------------- launch ------------------------------------------------------
extern "C" void kernel_launch(void* const* d_in, const int* in_sizes, int n_in,
                              void* d_out, int out_size) {
    (void)in_sizes; (void)n_in; (void)out_size;
    const float* x     = (const float*)d_in[0];
    const int*   batch = (const int*)d_in[1];
    const float* W1    = (const float*)d_in[2];
    const float* b1    = (const float*)d_in[3];
    const float* W2    = (const float*)d_in[4];
    const float* b2    = (const float*)d_in[5];
    float*       out   = (float*)d_out;

    cudaFuncSetAttribute(fused_kernel,
                         cudaFuncAttributeMaxDynamicSharedMemorySize,
                         SMEM_A_BYTES);

    zero_kernel<<<BB, DD>>>(out);
    w1h_kernel<<<DD / 2, HH>>>(W1);
    fused_kernel<<<NN / 256, 512, SMEM_A_BYTES>>>(x, batch, b1, W2, b2, out);
    normalize_kernel<<<BB, DD>>>(out);
}